// round 7
// baseline (speedup 1.0000x reference)
#include <cuda_runtime.h>
#include <cstdint>
#include <cstddef>

#define BQ   16
#define HDIM 64
#define WDIM 64
#define CIN  256
#define COUT 256
#define NTAP 9

#define TH 16
#define TW 8
#define NCO 64                     /* co per CTA */
#define BK 32                      /* ci per stage = one k32 chunk */
#define NCHUNK (CIN/BK)            /* 8 */
#define NS (NTAP*NCHUNK)           /* 72 stages */
#define WP 10
#define HP 18
#define NPIX 180
#define ROWB 48                    /* smem row: 32 B data + 16 B pad (conflict-free) */

#define SM_DEMOD 0                 /* 64 floats = 256 B */
#define SM_A     256
#define A_PLANE  (NPIX*ROWB)       /* 8640 */
#define A_BUF    (2*A_PLANE)       /* hi+lo per parity = 17280 */
#define SM_B     (SM_A + 2*A_BUF)  /* 34816 */
#define B_PLANE  (NCO*ROWB)        /* 3072 */
#define B_BUF    (2*B_PLANE)       /* 6144 */
#define SM_TOTAL (SM_B + 3*B_BUF)  /* 53248 -> 2 CTAs/SM */

// Scratch (device globals; no runtime allocation)
__device__ unsigned char g_xhi[(size_t)BQ*HDIM*WDIM*CIN];   // 16.8 MB
__device__ unsigned char g_xlo[(size_t)BQ*HDIM*WDIM*CIN];
__device__ unsigned char g_whiT[NTAP*COUT*CIN];             // [tap][co][ci]
__device__ unsigned char g_wloT[NTAP*COUT*CIN];
__device__ float    g_dpart[BQ*NTAP*COUT];
__device__ float    g_demod[BQ*COUT];
__device__ unsigned g_sbits[2];                             // amax bits: [0]=x, [1]=w

// ---------------- prep kernels ----------------

__global__ void prep_init() {
    if (threadIdx.x < 2) g_sbits[threadIdx.x] = 0u;
}

__device__ __forceinline__ void amax_commit(float v, unsigned* dst) {
    #pragma unroll
    for (int o = 16; o; o >>= 1) v = fmaxf(v, __shfl_xor_sync(~0u, v, o));
    __shared__ float sred[8];
    int lane = threadIdx.x & 31, w = threadIdx.x >> 5;
    if (lane == 0) sred[w] = v;
    __syncthreads();
    if (threadIdx.x == 0) {
        float m = sred[0];
        #pragma unroll
        for (int i = 1; i < 8; ++i) m = fmaxf(m, sred[i]);
        atomicMax(dst, __float_as_uint(m));
    }
}

__global__ void prep_amax_x(const float* __restrict__ x,
                            const float* __restrict__ style) {
    float m = 0.0f;
    #pragma unroll 1
    for (int j = 0; j < 16; ++j) {
        int i = blockIdx.x*256 + threadIdx.x + j*262144;    // 4.19M float4 exact
        float4 v = reinterpret_cast<const float4*>(x)[i];
        int e = i << 2;
        int ci = e & (CIN-1);
        int b  = e >> 20;
        float4 s = reinterpret_cast<const float4*>(style)[(b*CIN + ci) >> 2];
        m = fmaxf(m, fabsf(v.x*(s.x+1.0f)));
        m = fmaxf(m, fabsf(v.y*(s.y+1.0f)));
        m = fmaxf(m, fabsf(v.z*(s.z+1.0f)));
        m = fmaxf(m, fabsf(v.w*(s.w+1.0f)));
    }
    amax_commit(m, &g_sbits[0]);
}

__global__ void prep_amax_w(const float* __restrict__ kern) {
    float m = 0.0f;
    #pragma unroll 1
    for (int t = blockIdx.x*256 + threadIdx.x; t < 147456; t += 16384) {
        float4 v = reinterpret_cast<const float4*>(kern)[t];
        m = fmaxf(fmaxf(fabsf(v.x), fabsf(v.y)), fmaxf(fmaxf(fabsf(v.z), fabsf(v.w)), m));
    }
    amax_commit(m, &g_sbits[1]);
}

__device__ __forceinline__ void q16_split(float v, float Q, int& hi, int& lo) {
    int q = __float2int_rn(v * Q);
    q = max(-32639, min(32639, q));
    hi = (q + 128) >> 8;
    lo = q - (hi << 8);
}

__global__ void prep_xq(const float* __restrict__ x,
                        const float* __restrict__ style) {
    float Sx = fmaxf(__uint_as_float(g_sbits[0]), 1e-20f);
    float Q  = 32512.0f / Sx;
    int i = blockIdx.x*256 + threadIdx.x;                   // float4 index, exact
    int e = i << 2;
    int ci = e & (CIN-1);
    int b  = e >> 20;
    float4 v = reinterpret_cast<const float4*>(x)[i];
    float4 s = reinterpret_cast<const float4*>(style)[(b*CIN + ci) >> 2];
    int h0,l0,h1,l1,h2,l2,h3,l3;
    q16_split(v.x*(s.x+1.0f), Q, h0, l0);
    q16_split(v.y*(s.y+1.0f), Q, h1, l1);
    q16_split(v.z*(s.z+1.0f), Q, h2, l2);
    q16_split(v.w*(s.w+1.0f), Q, h3, l3);
    unsigned hb = (h0&255) | ((h1&255)<<8) | ((h2&255)<<16) | ((unsigned)(h3&255)<<24);
    unsigned lb = (l0&255) | ((l1&255)<<8) | ((l2&255)<<16) | ((unsigned)(l3&255)<<24);
    reinterpret_cast<unsigned*>(g_xhi)[i] = hb;
    reinterpret_cast<unsigned*>(g_xlo)[i] = lb;
}

__global__ void prep_wqT(const float* __restrict__ kern) {
    // grid = NTAP*COUT blocks of 64 threads; block = tap*COUT+co; thread = 4 ci
    int tap = blockIdx.x >> 8;
    int co  = blockIdx.x & 255;
    float Sw = fmaxf(__uint_as_float(g_sbits[1]), 1e-20f);
    float Q  = 32512.0f / Sw;
    int ci0 = threadIdx.x << 2;
    int h[4], l[4];
    #pragma unroll
    for (int k = 0; k < 4; ++k) {
        float w = kern[(size_t)(tap*CIN + ci0 + k)*COUT + co];
        q16_split(w, Q, h[k], l[k]);
    }
    unsigned hb = (h[0]&255) | ((h[1]&255)<<8) | ((h[2]&255)<<16) | ((unsigned)(h[3]&255)<<24);
    unsigned lb = (l[0]&255) | ((l[1]&255)<<8) | ((l[2]&255)<<16) | ((unsigned)(l[3]&255)<<24);
    reinterpret_cast<unsigned*>(g_whiT)[blockIdx.x*64 + threadIdx.x] = hb;
    reinterpret_cast<unsigned*>(g_wloT)[blockIdx.x*64 + threadIdx.x] = lb;
}

__global__ void prep_demod_part(const float* __restrict__ kern,
                                const float* __restrict__ style) {
    int tap = blockIdx.x, b = blockIdx.y, co = threadIdx.x;
    float acc = 0.0f;
    #pragma unroll 4
    for (int ci = 0; ci < CIN; ++ci) {
        float s = style[b*CIN + ci] + 1.0f;
        float v = kern[((size_t)(tap*CIN + ci))*COUT + co];
        acc += v*v*s*s;
    }
    g_dpart[(b*NTAP + tap)*COUT + co] = acc;
}

__global__ void prep_demod_fin() {
    int b = blockIdx.x, co = threadIdx.x;
    float a = 0.0f;
    #pragma unroll
    for (int t = 0; t < NTAP; ++t) a += g_dpart[(b*NTAP + t)*COUT + co];
    g_demod[b*COUT + co] = rsqrtf(a + 1e-8f);
}

// ---------------- main implicit-GEMM conv (mma.sync s8, 3-pass) ----------------

__device__ __forceinline__ void imma(int* c, const uint32_t* a, const uint32_t* bf) {
    asm volatile(
        "mma.sync.aligned.m16n8k32.row.col.s32.s8.s8.s32 "
        "{%0,%1,%2,%3},{%4,%5,%6,%7},{%8,%9},{%0,%1,%2,%3};\n"
        : "+r"(c[0]), "+r"(c[1]), "+r"(c[2]), "+r"(c[3])
        : "r"(a[0]), "r"(a[1]), "r"(a[2]), "r"(a[3]), "r"(bf[0]), "r"(bf[1]));
}

__global__ void __launch_bounds__(256, 2) modconv_imma(float* __restrict__ out) {
    extern __shared__ char smem[];
    float* sdemod = reinterpret_cast<float*>(smem + SM_DEMOD);

    const int tid  = threadIdx.x;
    const int lane = tid & 31;
    const int wid  = tid >> 5;
    const int warp_m = wid >> 1;   // 0..3 (M 4x32)
    const int warp_n = wid & 1;    // 0..1 (N 2x32)
    const int gid = lane >> 2;
    const int tig = lane & 3;

    const int bt  = blockIdx.x;
    const int co0 = (bt & 3) << 6;         // 4 co-tiles of 64
    const int mt  = bt >> 2;
    const int b   = mt >> 5;
    const int tI  = mt & 31;
    const int h0  = (tI >> 3) << 4;
    const int w0  = (tI & 7) << 3;

    // A-fragment pixel byte-offsets in halo (origin +1,+1)
    int pixo[2][2];
    #pragma unroll
    for (int mf = 0; mf < 2; ++mf)
        #pragma unroll
        for (int hf = 0; hf < 2; ++hf) {
            int i  = warp_m*32 + mf*16 + hf*8 + gid;
            int hi = i >> 3, wi = i & 7;
            pixo[mf][hf] = ((hi + 1)*WP + (wi + 1)) * ROWB;
        }

    const uint32_t sbase = (uint32_t)__cvta_generic_to_shared(smem);

    if (tid < NCO) sdemod[tid] = g_demod[b*COUT + co0 + tid];

    auto stage_x = [&](int chunk) {
        const uint32_t ab = sbase + SM_A + (chunk & 1)*A_BUF;
        const int ci0 = chunk * BK;
        #pragma unroll 1
        for (int t = tid; t < NPIX*4; t += 256) {            // 720 x 16B
            int pix  = t >> 2;
            int limb = (t >> 1) & 1;
            int half = t & 1;
            int hh = pix / WP;
            int ww = pix - hh*WP;
            int gh = h0 - 1 + hh;
            int gw = w0 - 1 + ww;
            bool ok = ((unsigned)gh < HDIM) && ((unsigned)gw < WDIM);
            const unsigned char* base = limb ? g_xlo : g_xhi;
            const void* src = base;
            if (ok) src = base + ((size_t)((b*HDIM + gh)*WDIM + gw))*CIN + ci0 + half*16;
            int sz = ok ? 16 : 0;
            uint32_t dst = ab + limb*A_PLANE + pix*ROWB + half*16;
            asm volatile("cp.async.cg.shared.global [%0], [%1], 16, %2;\n"
                         :: "r"(dst), "l"(src), "r"(sz));
        }
    };

    auto stage_b = [&](int f) {
        int tap   = f % NTAP;
        int chunk = f / NTAP;
        uint32_t bb = sbase + SM_B + (f % 3)*B_BUF;
        int n    = tid >> 2;                                  // 256 tasks exactly
        int limb = (tid >> 1) & 1;
        int half = tid & 1;
        const unsigned char* base = limb ? g_wloT : g_whiT;
        const void* src = base + ((size_t)(tap*COUT + co0 + n))*CIN + chunk*BK + half*16;
        uint32_t dst = bb + limb*B_PLANE + n*ROWB + half*16;
        asm volatile("cp.async.cg.shared.global [%0], [%1], 16;\n"
                     :: "r"(dst), "l"(src));
    };

    auto fill = [&](int f) {
        if ((f % NTAP) == 0) stage_x(f / NTAP);
        stage_b(f);
        asm volatile("cp.async.commit_group;\n");
    };

    int accH[2][4][4], accM[2][4][4];
    #pragma unroll
    for (int mf = 0; mf < 2; ++mf)
        #pragma unroll
        for (int nf = 0; nf < 4; ++nf)
            #pragma unroll
            for (int r = 0; r < 4; ++r) { accH[mf][nf][r] = 0; accM[mf][nf][r] = 0; }

    fill(0);
    fill(1);

    #pragma unroll 1
    for (int s = 0; s < NS; ++s) {
        if (s + 2 < NS) asm volatile("cp.async.wait_group 1;\n");
        else            asm volatile("cp.async.wait_group 0;\n");
        __syncthreads();

        if (s + 2 < NS) fill(s + 2);

        const int tap   = s % NTAP;
        const int chunk = s / NTAP;
        const char* ap = smem + SM_A + (chunk & 1)*A_BUF;
        const char* bp = smem + SM_B + (s % 3)*B_BUF;
        const int toff = ((tap/3)*WP + (tap%3) - (WP + 1)) * ROWB;

        uint32_t ah[2][4], al[2][4], bh[4][2], bl[4][2];
        #pragma unroll
        for (int mf = 0; mf < 2; ++mf) {
            const char* p0 = ap + pixo[mf][0] + toff + tig*4;
            const char* p1 = ap + pixo[mf][1] + toff + tig*4;
            ah[mf][0] = *reinterpret_cast<const uint32_t*>(p0);
            ah[mf][1] = *reinterpret_cast<const uint32_t*>(p1);
            ah[mf][2] = *reinterpret_cast<const uint32_t*>(p0 + 16);
            ah[mf][3] = *reinterpret_cast<const uint32_t*>(p1 + 16);
            al[mf][0] = *reinterpret_cast<const uint32_t*>(p0 + A_PLANE);
            al[mf][1] = *reinterpret_cast<const uint32_t*>(p1 + A_PLANE);
            al[mf][2] = *reinterpret_cast<const uint32_t*>(p0 + A_PLANE + 16);
            al[mf][3] = *reinterpret_cast<const uint32_t*>(p1 + A_PLANE + 16);
        }
        #pragma unroll
        for (int nf = 0; nf < 4; ++nf) {
            int n = warp_n*32 + nf*8 + gid;
            const char* q = bp + n*ROWB + tig*4;
            bh[nf][0] = *reinterpret_cast<const uint32_t*>(q);
            bh[nf][1] = *reinterpret_cast<const uint32_t*>(q + 16);
            bl[nf][0] = *reinterpret_cast<const uint32_t*>(q + B_PLANE);
            bl[nf][1] = *reinterpret_cast<const uint32_t*>(q + B_PLANE + 16);
        }
        #pragma unroll
        for (int mf = 0; mf < 2; ++mf)
            #pragma unroll
            for (int nf = 0; nf < 4; ++nf) {
                imma(accH[mf][nf], ah[mf], bh[nf]);   // hi*hi   (x65536)
                imma(accM[mf][nf], ah[mf], bl[nf]);   // hi*lo   (x256)
                imma(accM[mf][nf], al[mf], bh[nf]);   // lo*hi   (x256)
            }
    }

    // Epilogue: y = (accH*65536 + accM*256) * Sx*Sw/32512^2 * demod
    {
        float Sx = __uint_as_float(g_sbits[0]);
        float Sw = __uint_as_float(g_sbits[1]);
        float C  = (Sx * Sw) / (32512.0f * 32512.0f);
        #pragma unroll
        for (int mf = 0; mf < 2; ++mf) {
            int i0 = warp_m*32 + mf*16 + gid;
            int hi = i0 >> 3, wi = i0 & 7;
            size_t r0 = ((size_t)((b*HDIM + h0 + hi)*WDIM + (w0 + wi))) * COUT;
            size_t r1 = r0 + (size_t)WDIM * COUT;     // pixel i0+8 -> next image row
            #pragma unroll
            for (int nf = 0; nf < 4; ++nf) {
                int cl = warp_n*32 + nf*8 + 2*tig;
                float d0 = sdemod[cl] * C, d1 = sdemod[cl + 1] * C;
                int col = co0 + cl;
                float2 v;
                v.x = ((float)accH[mf][nf][0]*65536.0f + (float)accM[mf][nf][0]*256.0f) * d0;
                v.y = ((float)accH[mf][nf][1]*65536.0f + (float)accM[mf][nf][1]*256.0f) * d1;
                *reinterpret_cast<float2*>(out + r0 + col) = v;
                v.x = ((float)accH[mf][nf][2]*65536.0f + (float)accM[mf][nf][2]*256.0f) * d0;
                v.y = ((float)accH[mf][nf][3]*65536.0f + (float)accM[mf][nf][3]*256.0f) * d1;
                *reinterpret_cast<float2*>(out + r1 + col) = v;
            }
        }
    }
}

// ---------------- launch ----------------

extern "C" void kernel_launch(void* const* d_in, const int* in_sizes, int n_in,
                              void* d_out, int out_size) {
    (void)in_sizes; (void)n_in; (void)out_size;
    const float* x     = (const float*)d_in[0];   // [16,64,64,256] f32
    const float* style = (const float*)d_in[1];   // [16,256] f32
    const float* kern  = (const float*)d_in[2];   // [3,3,256,256] f32
    float* out = (float*)d_out;                   // [16,64,64,256] f32

    cudaFuncSetAttribute(modconv_imma,
                         cudaFuncAttributeMaxDynamicSharedMemorySize, SM_TOTAL);

    prep_init<<<1, 32>>>();
    prep_amax_x<<<1024, 256>>>(x, style);
    prep_amax_w<<<64, 256>>>(kern);
    prep_xq<<<16384, 256>>>(x, style);
    prep_wqT<<<NTAP*COUT, 64>>>(kern);
    prep_demod_part<<<dim3(NTAP, BQ), COUT>>>(kern, style);
    prep_demod_fin<<<BQ, COUT>>>();
    modconv_imma<<<2048, 256, SM_TOTAL>>>(out);
}

// round 8
// speedup vs baseline: 3.6627x; 3.6627x over previous
#include <cuda_runtime.h>
#include <cstdint>
#include <cstddef>

#define BQ   16
#define HDIM 64
#define WDIM 64
#define CIN  256
#define COUT 256
#define NTAP 9

#define TH 16
#define TW 8
#define BK 32
#define NCHUNK (CIN/BK)            /* 8 */
#define NS (NTAP*NCHUNK)           /* 72 stages */
#define XS_PS 36                   /* floats per halo pixel: 32 ci + 4 pad */
#define BS_NS 136                  /* floats per B k-row: 128 + 8 pad */
#define HP (TH+2)
#define WP (TW+2)
#define NPIX (HP*WP)               /* 180 halo pixels */
#define NXT (NPIX*(BK/4))          /* 1440 float4 tasks per x stage */

/* dynamic smem layout (bytes) */
#define SM_DEMOD 0                          /* 256 f */
#define SM_STYLE 1024                       /* 256 f (style+1) */
#define SM_XS0   2048
#define XS_BYTES (NPIX*XS_PS*4)             /* 25920 */
#define SM_XS1   (SM_XS0 + XS_BYTES)        /* 27968 */
#define SM_BS    (SM_XS1 + XS_BYTES)        /* 53888 */
#define BS_BYTES (BK*BS_NS*4)               /* 17408 */
#define SM_TOTAL (SM_BS + 3*BS_BYTES)       /* 106112 */

// Scratch (device globals; no runtime allocation)
__device__ float g_wt[NTAP*CIN*COUT];                // tf32-rounded weights [tap][ci][co]
__device__ float g_dpart[BQ*NTAP*COUT];
__device__ float g_demod[BQ*COUT];

__device__ __forceinline__ float rna_tf32(float f) {
    uint32_t u;
    asm("cvt.rna.tf32.f32 %0, %1;" : "=r"(u) : "f"(f));
    return __uint_as_float(u);
}

// ---------------- prep kernels ----------------

// per (tap, b): partial demod sums; b==0 blocks also emit tf32-rounded weights
__global__ void prep_demod_part(const float* __restrict__ kern,
                                const float* __restrict__ style) {
    int tap = blockIdx.x;     // 9
    int b   = blockIdx.y;     // 16
    int co  = threadIdx.x;    // 256
    float acc = 0.0f;
    #pragma unroll 4
    for (int ci = 0; ci < CIN; ++ci) {
        float s = style[b*CIN + ci] + 1.0f;
        float v = kern[((size_t)(tap*CIN + ci))*COUT + co];
        if (b == 0) g_wt[((size_t)(tap*CIN + ci))*COUT + co] = rna_tf32(v);
        acc += v*v*s*s;
    }
    g_dpart[(b*NTAP + tap)*COUT + co] = acc;
}

__global__ void prep_demod_fin() {
    int b = blockIdx.x, co = threadIdx.x;
    float a = 0.0f;
    #pragma unroll
    for (int t = 0; t < NTAP; ++t) a += g_dpart[(b*NTAP + t)*COUT + co];
    g_demod[b*COUT + co] = rsqrtf(a + 1e-8f);
}

// ---------------- main implicit-GEMM conv (mma.sync tf32, fused modulation) ----------------

__global__ void __launch_bounds__(256, 2) modconv_kernel(const float* __restrict__ xg,
                                                         const float* __restrict__ style,
                                                         float* __restrict__ out) {
    extern __shared__ char smem[];
    float* sdemod = reinterpret_cast<float*>(smem + SM_DEMOD);
    float* sstyle = reinterpret_cast<float*>(smem + SM_STYLE);

    const int tid  = threadIdx.x;
    const int lane = tid & 31;
    const int wid  = tid >> 5;
    const int warp_m = wid >> 2;   // 0..1
    const int warp_n = wid & 3;    // 0..3
    const int gid = lane >> 2;
    const int tig = lane & 3;

    const int bt     = blockIdx.x;
    const int n_tile = bt & 1;
    const int mt     = bt >> 1;
    const int b      = mt >> 5;
    const int tI     = mt & 31;
    const int h0     = (tI >> 3) << 4;     // *16
    const int w0     = (tI & 7) << 3;      // *8
    const int co0    = n_tile << 7;        // *128

    // A-fragment pixel offsets (floats, already *XS_PS), halo origin (+1,+1)
    int pixo[8];
    #pragma unroll
    for (int mf = 0; mf < 4; ++mf) {
        #pragma unroll
        for (int hf = 0; hf < 2; ++hf) {
            int i  = warp_m*64 + mf*16 + hf*8 + gid;
            int hi = i >> 3, wi = i & 7;
            pixo[mf*2 + hf] = ((hi + 1)*WP + (wi + 1)) * XS_PS;
        }
    }

    const uint32_t sbase = (uint32_t)__cvta_generic_to_shared(smem);

    // load demod + style rows, then barrier before first x stage uses sstyle
    sdemod[tid] = g_demod[b*COUT + tid];
    sstyle[tid] = style[b*CIN + tid] + 1.0f;
    __syncthreads();

    // Fused x stage: LDG raw x (3-deep batches), modulate, rna, STS
    auto stage_x = [&](int chunk) {
        float* xb = reinterpret_cast<float*>(smem + ((chunk & 1) ? SM_XS1 : SM_XS0));
        const int ci0 = chunk * BK;
        #pragma unroll 1
        for (int t0 = 0; t0 < NXT; t0 += 768) {
            float4 v[3];
            float4 sc[3];
            int    off[3];
            #pragma unroll
            for (int j = 0; j < 3; ++j) {
                int t = t0 + tid + j*256;
                off[j] = -1;
                if (t < NXT) {
                    int pix = t >> 3;
                    int c4  = t & 7;
                    int hh  = pix / WP;
                    int ww  = pix - hh * WP;
                    int gh  = h0 - 1 + hh;
                    int gw  = w0 - 1 + ww;
                    off[j] = pix*XS_PS + c4*4;
                    sc[j]  = *reinterpret_cast<const float4*>(sstyle + ci0 + c4*4);
                    if (((unsigned)gh < HDIM) && ((unsigned)gw < WDIM)) {
                        v[j] = *reinterpret_cast<const float4*>(
                            xg + ((size_t)((b*HDIM + gh)*WDIM + gw))*CIN + ci0 + c4*4);
                    } else {
                        v[j] = make_float4(0.f, 0.f, 0.f, 0.f);
                        sc[j] = make_float4(0.f, 0.f, 0.f, 0.f);
                    }
                }
            }
            #pragma unroll
            for (int j = 0; j < 3; ++j) {
                if (off[j] >= 0) {
                    float4 r;
                    r.x = rna_tf32(v[j].x * sc[j].x);
                    r.y = rna_tf32(v[j].y * sc[j].y);
                    r.z = rna_tf32(v[j].z * sc[j].z);
                    r.w = rna_tf32(v[j].w * sc[j].w);
                    *reinterpret_cast<float4*>(xb + off[j]) = r;
                }
            }
        }
    };

    auto stage_b = [&](int f) {
        int tap   = f % NTAP;
        int chunk = f / NTAP;
        int krow  = tap*CIN + chunk*BK;
        uint32_t base = sbase + SM_BS + (f % 3)*BS_BYTES;
        #pragma unroll 1
        for (int t = tid; t < BK * 32; t += 256) {            // 1024 float4 tasks
            int kr = t >> 5;
            int n4 = t & 31;
            const float* src = g_wt + (size_t)(krow + kr)*COUT + co0 + n4*4;
            uint32_t dst = base + (uint32_t)(kr*BS_NS + n4*4) * 4u;
            asm volatile("cp.async.cg.shared.global [%0], [%1], 16;\n"
                         :: "r"(dst), "l"(src));
        }
    };

    auto fill = [&](int f) {
        if ((f % NTAP) == 0) stage_x(f / NTAP);
        stage_b(f);
        asm volatile("cp.async.commit_group;\n");
    };

    float acc[4][4][4];
    #pragma unroll
    for (int mf = 0; mf < 4; ++mf)
        #pragma unroll
        for (int nf = 0; nf < 4; ++nf)
            #pragma unroll
            for (int r = 0; r < 4; ++r) acc[mf][nf][r] = 0.0f;

    // Prologue: stages 0 and 1 in flight (x STS done in program order before first barrier)
    fill(0);
    fill(1);

    #pragma unroll 1
    for (int s = 0; s < NS; ++s) {
        // B group for stage s complete; allow stage s+1's group in flight.
        if (s + 2 < NS) asm volatile("cp.async.wait_group 1;\n");
        else            asm volatile("cp.async.wait_group 0;\n");
        // one barrier: (a) stage-s data visible (B via wait_group, x via program order
        // two barriers ago), (b) all warps done with stage s-1 -> buffers reusable
        __syncthreads();

        if (s + 2 < NS) fill(s + 2);

        const int tap   = s % NTAP;
        const int chunk = s / NTAP;
        const float* xsp = reinterpret_cast<const float*>(
            smem + ((chunk & 1) ? SM_XS1 : SM_XS0));
        const float* bsp = reinterpret_cast<const float*>(
            smem + SM_BS + (s % 3)*BS_BYTES);
        const int toff = ((tap/3)*WP + (tap%3) - (WP + 1)) * XS_PS;

        #pragma unroll
        for (int kk = 0; kk < BK; kk += 8) {
            uint32_t afr[4][4], bfr[4][2];
            #pragma unroll
            for (int mf = 0; mf < 4; ++mf) {
                const float* p0 = xsp + pixo[mf*2 + 0] + toff + kk + tig;
                const float* p1 = xsp + pixo[mf*2 + 1] + toff + kk + tig;
                afr[mf][0] = __float_as_uint(p0[0]);
                afr[mf][1] = __float_as_uint(p1[0]);
                afr[mf][2] = __float_as_uint(p0[4]);
                afr[mf][3] = __float_as_uint(p1[4]);
            }
            #pragma unroll
            for (int nf = 0; nf < 4; ++nf) {
                int n = warp_n*32 + nf*8 + gid;
                bfr[nf][0] = __float_as_uint(bsp[(kk + tig    )*BS_NS + n]);
                bfr[nf][1] = __float_as_uint(bsp[(kk + tig + 4)*BS_NS + n]);
            }
            #pragma unroll
            for (int mf = 0; mf < 4; ++mf) {
                #pragma unroll
                for (int nf = 0; nf < 4; ++nf) {
                    asm volatile(
                        "mma.sync.aligned.m16n8k8.row.col.f32.tf32.tf32.f32 "
                        "{%0,%1,%2,%3}, {%4,%5,%6,%7}, {%8,%9}, {%0,%1,%2,%3};\n"
                        : "+f"(acc[mf][nf][0]), "+f"(acc[mf][nf][1]),
                          "+f"(acc[mf][nf][2]), "+f"(acc[mf][nf][3])
                        : "r"(afr[mf][0]), "r"(afr[mf][1]),
                          "r"(afr[mf][2]), "r"(afr[mf][3]),
                          "r"(bfr[nf][0]), "r"(bfr[nf][1]));
                }
            }
        }
    }

    // Epilogue: scale by demod (from smem), coalesced float2 stores
    #pragma unroll
    for (int mf = 0; mf < 4; ++mf) {
        int i0 = warp_m*64 + mf*16 + gid;
        int hi = i0 >> 3, wi = i0 & 7;
        size_t r0 = ((size_t)((b*HDIM + h0 + hi)*WDIM + (w0 + wi))) * COUT;
        size_t r1 = r0 + (size_t)WDIM * COUT;     // pixel i0+8 -> next image row
        #pragma unroll
        for (int nf = 0; nf < 4; ++nf) {
            int col = co0 + warp_n*32 + nf*8 + 2*tig;
            float dx = sdemod[col], dy = sdemod[col + 1];
            float2 v;
            v.x = acc[mf][nf][0] * dx;
            v.y = acc[mf][nf][1] * dy;
            *reinterpret_cast<float2*>(out + r0 + col) = v;
            v.x = acc[mf][nf][2] * dx;
            v.y = acc[mf][nf][3] * dy;
            *reinterpret_cast<float2*>(out + r1 + col) = v;
        }
    }
}

// ---------------- launch ----------------

extern "C" void kernel_launch(void* const* d_in, const int* in_sizes, int n_in,
                              void* d_out, int out_size) {
    (void)in_sizes; (void)n_in; (void)out_size;
    const float* x     = (const float*)d_in[0];   // [16,64,64,256] f32
    const float* style = (const float*)d_in[1];   // [16,256] f32
    const float* kern  = (const float*)d_in[2];   // [3,3,256,256] f32
    float* out = (float*)d_out;                   // [16,64,64,256] f32

    cudaFuncSetAttribute(modconv_kernel,
                         cudaFuncAttributeMaxDynamicSharedMemorySize, SM_TOTAL);

    prep_demod_part<<<dim3(NTAP, BQ), COUT>>>(kern, style);      // 144 blocks (+w round)
    prep_demod_fin<<<BQ, COUT>>>();                              // 16 blocks
    modconv_kernel<<<(BQ*HDIM*WDIM/(TH*TW)) * (COUT/128), 256, SM_TOTAL>>>(x, style, out);
}

// round 10
// speedup vs baseline: 3.9063x; 1.0665x over previous
#include <cuda_runtime.h>
#include <cstdint>
#include <cstddef>

#define BQ   16
#define HDIM 64
#define WDIM 64
#define CIN  256
#define COUT 256
#define NTAP 9

#define TH 16
#define TW 8
#define BK 32
#define NCHUNK (CIN/BK)            /* 8 */
#define NS (NTAP*NCHUNK)           /* 72 stages */
#define XS_PS 36                   /* floats per halo pixel: 32 ci + 4 pad */
#define BS_NS 136                  /* floats per B k-row: 128 + 8 pad */
#define HP (TH+2)
#define WP (TW+2)
#define NPIX (HP*WP)               /* 180 halo pixels */

/* dynamic smem layout (bytes) */
#define SM_DEMOD 0                          /* 256 f */
#define SM_XS0   1024
#define XS_BYTES (NPIX*XS_PS*4)             /* 25920 */
#define SM_XS1   (SM_XS0 + XS_BYTES)        /* 26944 */
#define SM_BS    (SM_XS1 + XS_BYTES)        /* 52864 */
#define BS_BYTES (BK*BS_NS*4)               /* 17408 */
#define SM_TOTAL (SM_BS + 3*BS_BYTES)       /* 105088 */

// Scratch (device globals; no runtime allocation)
__device__ float g_xmod[(size_t)BQ*HDIM*WDIM*CIN];   // modulated + tf32-rounded x
__device__ float g_wt[NTAP*CIN*COUT];                // tf32-rounded weights [tap][ci][co]
__device__ float g_w2[CIN*COUT];                     // sum over taps of w^2
__device__ float g_dpart[BQ*4*COUT];
__device__ float g_demod[BQ*COUT];

__device__ __forceinline__ float rna_tf32(float f) {
    uint32_t u;
    asm("cvt.rna.tf32.f32 %0, %1;" : "=r"(u) : "f"(f));
    return __uint_as_float(u);
}

// ---------------- prep kernels ----------------

// One pass over kernel: tf32-rounded copy + per-(ci,co) tap-sum of squares.
__global__ void prep_w_kernel(const float* __restrict__ kern) {
    int ci = blockIdx.x;           // 256
    int co = threadIdx.x;          // 256
    float acc = 0.0f;
    #pragma unroll
    for (int tap = 0; tap < NTAP; ++tap) {
        float v = kern[((size_t)(tap*CIN + ci))*COUT + co];
        g_wt[((size_t)(tap*CIN + ci))*COUT + co] = rna_tf32(v);
        acc += v*v;
    }
    g_w2[ci*COUT + co] = acc;
}

// Partial demod: grid (BQ, 4); each block sums 64 ci against L2-resident W2.
__global__ void prep_demod_part(const float* __restrict__ style) {
    int b  = blockIdx.x;
    int q  = blockIdx.y;           // ci quarter
    int co = threadIdx.x;
    int ci0 = q * 64;
    float acc = 0.0f;
    #pragma unroll 8
    for (int i = 0; i < 64; ++i) {
        float s = style[b*CIN + ci0 + i] + 1.0f;
        acc += s*s * g_w2[(ci0 + i)*COUT + co];
    }
    g_dpart[(b*4 + q)*COUT + co] = acc;
}

__global__ void prep_demod_fin() {
    int b = blockIdx.x, co = threadIdx.x;
    float a = (g_dpart[(b*4+0)*COUT+co] + g_dpart[(b*4+1)*COUT+co])
            + (g_dpart[(b*4+2)*COUT+co] + g_dpart[(b*4+3)*COUT+co]);
    g_demod[b*COUT + co] = rsqrtf(a + 1e-8f);
}

__global__ void prep_x_kernel(const float* __restrict__ x,
                              const float* __restrict__ style) {
    int i = blockIdx.x * blockDim.x + threadIdx.x;          // float4 index, exact grid
    int e = i << 2;
    int ci = e & (CIN - 1);
    int b  = e >> 20;                                       // 2^20 elems per sample
    float4 v = reinterpret_cast<const float4*>(x)[i];
    float4 s = reinterpret_cast<const float4*>(style)[(b*CIN + ci) >> 2];
    v.x = rna_tf32(v.x * (s.x + 1.0f));
    v.y = rna_tf32(v.y * (s.y + 1.0f));
    v.z = rna_tf32(v.z * (s.z + 1.0f));
    v.w = rna_tf32(v.w * (s.w + 1.0f));
    reinterpret_cast<float4*>(g_xmod)[i] = v;
}

// ---------------- main implicit-GEMM conv (mma.sync tf32) ----------------

__global__ void __launch_bounds__(256, 2) modconv_kernel(float* __restrict__ out) {
    extern __shared__ char smem[];
    float* sdemod = reinterpret_cast<float*>(smem + SM_DEMOD);

    const int tid  = threadIdx.x;
    const int lane = tid & 31;
    const int wid  = tid >> 5;
    const int warp_m = wid >> 2;   // 0..1
    const int warp_n = wid & 3;    // 0..3
    const int gid = lane >> 2;
    const int tig = lane & 3;

    const int bt     = blockIdx.x;
    const int n_tile = bt & 1;
    const int mt     = bt >> 1;
    const int b      = mt >> 5;
    const int tI     = mt & 31;
    const int h0     = (tI >> 3) << 4;     // *16
    const int w0     = (tI & 7) << 3;      // *8
    const int co0    = n_tile << 7;        // *128

    // A-fragment pixel offsets (floats, already *XS_PS), halo origin (+1,+1)
    int pixo[8];
    #pragma unroll
    for (int mf = 0; mf < 4; ++mf) {
        #pragma unroll
        for (int hf = 0; hf < 2; ++hf) {
            int i  = warp_m*64 + mf*16 + hf*8 + gid;
            int hi = i >> 3, wi = i & 7;
            pixo[mf*2 + hf] = ((hi + 1)*WP + (wi + 1)) * XS_PS;
        }
    }

    const uint32_t sbase = (uint32_t)__cvta_generic_to_shared(smem);

    // load demod row
    sdemod[tid] = g_demod[b*COUT + tid];

    auto stage_x = [&](int chunk) {
        const uint32_t xb = sbase + ((chunk & 1) ? SM_XS1 : SM_XS0);
        const int ci0 = chunk * BK;
        #pragma unroll 1
        for (int t = tid; t < NPIX * (BK/4); t += 256) {      // 1440 float4 tasks
            int pix = t >> 3;
            int c4  = t & 7;
            int hh  = pix / WP;
            int ww  = pix - hh * WP;
            int gh  = h0 - 1 + hh;
            int gw  = w0 - 1 + ww;
            bool ok = ((unsigned)gh < HDIM) && ((unsigned)gw < WDIM);
            const float* src = g_xmod;
            if (ok) src = g_xmod + ((size_t)((b*HDIM + gh)*WDIM + gw))*CIN + ci0 + c4*4;
            int sz = ok ? 16 : 0;
            uint32_t dst = xb + (uint32_t)(pix*XS_PS + c4*4) * 4u;
            asm volatile("cp.async.cg.shared.global [%0], [%1], 16, %2;\n"
                         :: "r"(dst), "l"(src), "r"(sz));
        }
    };

    auto stage_b = [&](int f) {
        int tap   = f % NTAP;
        int chunk = f / NTAP;
        int krow  = tap*CIN + chunk*BK;
        uint32_t base = sbase + SM_BS + (f % 3)*BS_BYTES;
        #pragma unroll 1
        for (int t = tid; t < BK * 32; t += 256) {            // 1024 float4 tasks
            int kr = t >> 5;
            int n4 = t & 31;
            const float* src = g_wt + (size_t)(krow + kr)*COUT + co0 + n4*4;
            uint32_t dst = base + (uint32_t)(kr*BS_NS + n4*4) * 4u;
            asm volatile("cp.async.cg.shared.global [%0], [%1], 16;\n"
                         :: "r"(dst), "l"(src));
        }
    };

    auto fill = [&](int f) {
        if ((f % NTAP) == 0) stage_x(f / NTAP);
        stage_b(f);
        asm volatile("cp.async.commit_group;\n");
    };

    float acc[4][4][4];
    #pragma unroll
    for (int mf = 0; mf < 4; ++mf)
        #pragma unroll
        for (int nf = 0; nf < 4; ++nf)
            #pragma unroll
            for (int r = 0; r < 4; ++r) acc[mf][nf][r] = 0.0f;

    // Prologue: stages 0 and 1 in flight
    fill(0);
    fill(1);

    #pragma unroll 1
    for (int s = 0; s < NS; ++s) {
        // group for stage s complete (own copies); allow stage s+1's group in flight
        if (s + 2 < NS) asm volatile("cp.async.wait_group 1;\n");
        else            asm volatile("cp.async.wait_group 0;\n");
        // one barrier: (a) stage-s data visible to all warps,
        // (b) all warps done with stage s-1 MMAs -> B buf (s+2)%3 and xs buf reusable
        __syncthreads();

        if (s + 2 < NS) fill(s + 2);

        const int tap   = s % NTAP;
        const int chunk = s / NTAP;
        const float* xsp = reinterpret_cast<const float*>(
            smem + ((chunk & 1) ? SM_XS1 : SM_XS0));
        const float* bsp = reinterpret_cast<const float*>(
            smem + SM_BS + (s % 3)*BS_BYTES);
        const int toff = ((tap/3)*WP + (tap%3) - (WP + 1)) * XS_PS;

        #pragma unroll
        for (int kk = 0; kk < BK; kk += 8) {
            uint32_t afr[4][4], bfr[4][2];
            #pragma unroll
            for (int mf = 0; mf < 4; ++mf) {
                const float* p0 = xsp + pixo[mf*2 + 0] + toff + kk + tig;
                const float* p1 = xsp + pixo[mf*2 + 1] + toff + kk + tig;
                afr[mf][0] = __float_as_uint(p0[0]);
                afr[mf][1] = __float_as_uint(p1[0]);
                afr[mf][2] = __float_as_uint(p0[4]);
                afr[mf][3] = __float_as_uint(p1[4]);
            }
            #pragma unroll
            for (int nf = 0; nf < 4; ++nf) {
                int n = warp_n*32 + nf*8 + gid;
                bfr[nf][0] = __float_as_uint(bsp[(kk + tig    )*BS_NS + n]);
                bfr[nf][1] = __float_as_uint(bsp[(kk + tig + 4)*BS_NS + n]);
            }
            #pragma unroll
            for (int mf = 0; mf < 4; ++mf) {
                #pragma unroll
                for (int nf = 0; nf < 4; ++nf) {
                    asm volatile(
                        "mma.sync.aligned.m16n8k8.row.col.f32.tf32.tf32.f32 "
                        "{%0,%1,%2,%3}, {%4,%5,%6,%7}, {%8,%9}, {%0,%1,%2,%3};\n"
                        : "+f"(acc[mf][nf][0]), "+f"(acc[mf][nf][1]),
                          "+f"(acc[mf][nf][2]), "+f"(acc[mf][nf][3])
                        : "r"(afr[mf][0]), "r"(afr[mf][1]),
                          "r"(afr[mf][2]), "r"(afr[mf][3]),
                          "r"(bfr[nf][0]), "r"(bfr[nf][1]));
                }
            }
        }
    }

    // Epilogue: scale by demod (from smem), coalesced float2 stores
    #pragma unroll
    for (int mf = 0; mf < 4; ++mf) {
        int i0 = warp_m*64 + mf*16 + gid;
        int hi = i0 >> 3, wi = i0 & 7;
        size_t r0 = ((size_t)((b*HDIM + h0 + hi)*WDIM + (w0 + wi))) * COUT;
        size_t r1 = r0 + (size_t)WDIM * COUT;     // pixel i0+8 -> next image row
        #pragma unroll
        for (int nf = 0; nf < 4; ++nf) {
            int col = co0 + warp_n*32 + nf*8 + 2*tig;
            float dx = sdemod[col], dy = sdemod[col + 1];
            float2 v;
            v.x = acc[mf][nf][0] * dx;
            v.y = acc[mf][nf][1] * dy;
            *reinterpret_cast<float2*>(out + r0 + col) = v;
            v.x = acc[mf][nf][2] * dx;
            v.y = acc[mf][nf][3] * dy;
            *reinterpret_cast<float2*>(out + r1 + col) = v;
        }
    }
}

// ---------------- launch ----------------

extern "C" void kernel_launch(void* const* d_in, const int* in_sizes, int n_in,
                              void* d_out, int out_size) {
    (void)in_sizes; (void)n_in; (void)out_size;
    const float* x     = (const float*)d_in[0];   // [16,64,64,256] f32
    const float* style = (const float*)d_in[1];   // [16,256] f32
    const float* kern  = (const float*)d_in[2];   // [3,3,256,256] f32
    float* out = (float*)d_out;                   // [16,64,64,256] f32

    cudaFuncSetAttribute(modconv_kernel,
                         cudaFuncAttributeMaxDynamicSharedMemorySize, SM_TOTAL);

    prep_w_kernel<<<CIN, COUT>>>(kern);                      // 256 blocks, one kern pass
    prep_demod_part<<<dim3(BQ, 4), COUT>>>(style);           // 64 tiny blocks
    prep_demod_fin<<<BQ, COUT>>>();                          // 16 blocks
    prep_x_kernel<<<(int)(((size_t)BQ*HDIM*WDIM*CIN/4)/256), 256>>>(x, style);
    modconv_kernel<<<(BQ*HDIM*WDIM/(TH*TW)) * (COUT/128), 256, SM_TOTAL>>>(out);
}

// round 11
// speedup vs baseline: 6.8092x; 1.7431x over previous
#include <cuda_runtime.h>
#include <cuda_fp16.h>
#include <cstdint>
#include <cstddef>

#define BQ   16
#define HDIM 64
#define WDIM 64
#define CIN  256
#define COUT 256
#define NTAP 9

#define TH 16
#define TW 8
#define BK 64                      /* ci per stage (f16) */
#define NCHUNK (CIN/BK)            /* 4 */
#define NS (NTAP*NCHUNK)           /* 36 stages */
#define HP (TH+2)
#define WP (TW+2)
#define NPIX (HP*WP)               /* 180 halo pixels */
#define PITCH 144                  /* bytes per pixel row / B row: 128 data + 16 pad */

/* dynamic smem layout (bytes) */
#define SM_DEMOD 0                          /* 256 f32 */
#define SM_XS0   1024
#define XS_BYTES (NPIX*PITCH)               /* 25920 */
#define SM_XS1   (SM_XS0 + XS_BYTES)        /* 26944 */
#define SM_BS    (SM_XS1 + XS_BYTES)        /* 52864 */
#define BS_BYTES (128*PITCH)                /* 18432 */
#define SM_TOTAL (SM_BS + 3*BS_BYTES)       /* 108160 */

// Scratch (device globals; no runtime allocation)
__device__ __half g_xmod[(size_t)BQ*HDIM*WDIM*CIN];   // modulated x, f16 (32 MB)
__device__ __half g_wtT[(size_t)NTAP*COUT*CIN];       // f16 weights [tap][co][ci]
__device__ float  g_w2[CIN*COUT];                     // sum over taps of w^2
__device__ float  g_dpart[BQ*4*COUT];
__device__ float  g_demod[BQ*COUT];

// ---------------- prep kernels ----------------

// Transpose + f16 convert: grid (NTAP, 16 ci-groups), 256 thr = co.
__global__ void prep_wT(const float* __restrict__ kern) {
    int tap = blockIdx.x;
    int cig = blockIdx.y;           // 16 ci per group
    int co  = threadIdx.x;
    __half h[16];
    #pragma unroll
    for (int i = 0; i < 16; ++i) {
        int ci = cig*16 + i;
        h[i] = __float2half_rn(kern[((size_t)(tap*CIN + ci))*COUT + co]);  // coalesced
    }
    // one 32-byte sector per thread
    *reinterpret_cast<uint4*>(g_wtT + ((size_t)(tap*COUT + co))*CIN + cig*16) =
        *reinterpret_cast<const uint4*>(h);
    *reinterpret_cast<uint4*>(g_wtT + ((size_t)(tap*COUT + co))*CIN + cig*16 + 8) =
        *reinterpret_cast<const uint4*>(h + 8);
}

// per-(ci,co) tap-sum of squares (fp32, for demod)
__global__ void prep_w2(const float* __restrict__ kern) {
    int ci = blockIdx.x;            // 256
    int co = threadIdx.x;           // 256
    float acc = 0.0f;
    #pragma unroll
    for (int tap = 0; tap < NTAP; ++tap) {
        float v = kern[((size_t)(tap*CIN + ci))*COUT + co];
        acc += v*v;
    }
    g_w2[ci*COUT + co] = acc;
}

__global__ void prep_demod_part(const float* __restrict__ style) {
    int b  = blockIdx.x;
    int q  = blockIdx.y;
    int co = threadIdx.x;
    int ci0 = q * 64;
    float acc = 0.0f;
    #pragma unroll 8
    for (int i = 0; i < 64; ++i) {
        float s = style[b*CIN + ci0 + i] + 1.0f;
        acc += s*s * g_w2[(ci0 + i)*COUT + co];
    }
    g_dpart[(b*4 + q)*COUT + co] = acc;
}

__global__ void prep_demod_fin() {
    int b = blockIdx.x, co = threadIdx.x;
    float a = (g_dpart[(b*4+0)*COUT+co] + g_dpart[(b*4+1)*COUT+co])
            + (g_dpart[(b*4+2)*COUT+co] + g_dpart[(b*4+3)*COUT+co]);
    g_demod[b*COUT + co] = rsqrtf(a + 1e-8f);
}

__global__ void prep_x(const float* __restrict__ x,
                       const float* __restrict__ style) {
    int i = blockIdx.x * blockDim.x + threadIdx.x;     // float4 index, exact grid
    int e = i << 2;
    int ci = e & (CIN - 1);
    int b  = e >> 20;
    float4 v = reinterpret_cast<const float4*>(x)[i];
    float4 s = reinterpret_cast<const float4*>(style)[(b*CIN + ci) >> 2];
    __half2 h01 = __floats2half2_rn(v.x*(s.x+1.0f), v.y*(s.y+1.0f));
    __half2 h23 = __floats2half2_rn(v.z*(s.z+1.0f), v.w*(s.w+1.0f));
    uint2 pk;
    pk.x = *reinterpret_cast<uint32_t*>(&h01);
    pk.y = *reinterpret_cast<uint32_t*>(&h23);
    reinterpret_cast<uint2*>(g_xmod)[i] = pk;
}

// ---------------- main implicit-GEMM conv (mma.sync f16 m16n8k16) ----------------

__global__ void __launch_bounds__(256, 2) modconv_kernel(float* __restrict__ out) {
    extern __shared__ char smem[];
    float* sdemod = reinterpret_cast<float*>(smem + SM_DEMOD);

    const int tid  = threadIdx.x;
    const int lane = tid & 31;
    const int wid  = tid >> 5;
    const int warp_m = wid >> 2;   // 0..1  (M 2x64)
    const int warp_n = wid & 3;    // 0..3  (N 4x32)
    const int gid = lane >> 2;
    const int tig = lane & 3;

    const int bt     = blockIdx.x;
    const int n_tile = bt & 1;
    const int mt     = bt >> 1;
    const int b      = mt >> 5;
    const int tI     = mt & 31;
    const int h0     = (tI >> 3) << 4;     // *16
    const int w0     = (tI & 7) << 3;      // *8
    const int co0    = n_tile << 7;        // *128

    // A-fragment pixel byte offsets, halo origin (+1,+1)
    int pixo[8];
    #pragma unroll
    for (int mf = 0; mf < 4; ++mf) {
        #pragma unroll
        for (int hf = 0; hf < 2; ++hf) {
            int i  = warp_m*64 + mf*16 + hf*8 + gid;
            int hi = i >> 3, wi = i & 7;
            pixo[mf*2 + hf] = ((hi + 1)*WP + (wi + 1)) * PITCH;
        }
    }

    const uint32_t sbase = (uint32_t)__cvta_generic_to_shared(smem);

    sdemod[tid] = g_demod[b*COUT + tid];

    auto stage_x = [&](int chunk) {
        const uint32_t xb = sbase + ((chunk & 1) ? SM_XS1 : SM_XS0);
        const int ci0 = chunk * BK;
        #pragma unroll 1
        for (int t = tid; t < NPIX * 8; t += 256) {           // 1440 x 16B
            int pix = t >> 3;
            int c4  = t & 7;
            int hh  = pix / WP;
            int ww  = pix - hh * WP;
            int gh  = h0 - 1 + hh;
            int gw  = w0 - 1 + ww;
            bool ok = ((unsigned)gh < HDIM) && ((unsigned)gw < WDIM);
            const void* src = g_xmod;
            if (ok) src = g_xmod + ((size_t)((b*HDIM + gh)*WDIM + gw))*CIN + ci0 + c4*8;
            int sz = ok ? 16 : 0;
            uint32_t dst = xb + (uint32_t)(pix*PITCH + c4*16);
            asm volatile("cp.async.cg.shared.global [%0], [%1], 16, %2;\n"
                         :: "r"(dst), "l"(src), "r"(sz));
        }
    };

    auto stage_b = [&](int f) {
        int tap   = f % NTAP;
        int chunk = f / NTAP;
        uint32_t base = sbase + SM_BS + (f % 3)*BS_BYTES;
        #pragma unroll 1
        for (int t = tid; t < 128 * 8; t += 256) {            // 1024 x 16B
            int n  = t >> 3;
            int c4 = t & 7;
            const void* src = g_wtT + ((size_t)(tap*COUT + co0 + n))*CIN
                              + chunk*BK + c4*8;
            uint32_t dst = base + (uint32_t)(n*PITCH + c4*16);
            asm volatile("cp.async.cg.shared.global [%0], [%1], 16;\n"
                         :: "r"(dst), "l"(src));
        }
    };

    auto fill = [&](int f) {
        if ((f % NTAP) == 0) stage_x(f / NTAP);
        stage_b(f);
        asm volatile("cp.async.commit_group;\n");
    };

    float acc[4][4][4];
    #pragma unroll
    for (int mf = 0; mf < 4; ++mf)
        #pragma unroll
        for (int nf = 0; nf < 4; ++nf)
            #pragma unroll
            for (int r = 0; r < 4; ++r) acc[mf][nf][r] = 0.0f;

    fill(0);
    fill(1);

    #pragma unroll 1
    for (int s = 0; s < NS; ++s) {
        if (s + 2 < NS) asm volatile("cp.async.wait_group 1;\n");
        else            asm volatile("cp.async.wait_group 0;\n");
        // one barrier: stage-s data visible; stage s-1 compute done -> buffers reusable
        __syncthreads();

        if (s + 2 < NS) fill(s + 2);

        const int tap   = s % NTAP;
        const int chunk = s / NTAP;
        const char* xsp = smem + ((chunk & 1) ? SM_XS1 : SM_XS0);
        const char* bsp = smem + SM_BS + (s % 3)*BS_BYTES;
        const int toff = ((tap/3)*WP + (tap%3) - (WP + 1)) * PITCH;

        #pragma unroll
        for (int kk = 0; kk < BK/16; ++kk) {     // 4 k16 iterations
            const int koff = kk*32;
            uint32_t afr[4][4], bfr[4][2];
            #pragma unroll
            for (int mf = 0; mf < 4; ++mf) {
                const char* p0 = xsp + pixo[mf*2 + 0] + toff + koff + tig*4;
                const char* p1 = xsp + pixo[mf*2 + 1] + toff + koff + tig*4;
                afr[mf][0] = *reinterpret_cast<const uint32_t*>(p0);
                afr[mf][1] = *reinterpret_cast<const uint32_t*>(p1);
                afr[mf][2] = *reinterpret_cast<const uint32_t*>(p0 + 16);
                afr[mf][3] = *reinterpret_cast<const uint32_t*>(p1 + 16);
            }
            #pragma unroll
            for (int nf = 0; nf < 4; ++nf) {
                int n = warp_n*32 + nf*8 + gid;
                const char* q = bsp + n*PITCH + koff + tig*4;
                bfr[nf][0] = *reinterpret_cast<const uint32_t*>(q);
                bfr[nf][1] = *reinterpret_cast<const uint32_t*>(q + 16);
            }
            #pragma unroll
            for (int mf = 0; mf < 4; ++mf) {
                #pragma unroll
                for (int nf = 0; nf < 4; ++nf) {
                    asm volatile(
                        "mma.sync.aligned.m16n8k16.row.col.f32.f16.f16.f32 "
                        "{%0,%1,%2,%3}, {%4,%5,%6,%7}, {%8,%9}, {%0,%1,%2,%3};\n"
                        : "+f"(acc[mf][nf][0]), "+f"(acc[mf][nf][1]),
                          "+f"(acc[mf][nf][2]), "+f"(acc[mf][nf][3])
                        : "r"(afr[mf][0]), "r"(afr[mf][1]),
                          "r"(afr[mf][2]), "r"(afr[mf][3]),
                          "r"(bfr[nf][0]), "r"(bfr[nf][1]));
                }
            }
        }
    }

    // Epilogue: scale by demod, coalesced float2 stores
    #pragma unroll
    for (int mf = 0; mf < 4; ++mf) {
        int i0 = warp_m*64 + mf*16 + gid;
        int hi = i0 >> 3, wi = i0 & 7;
        size_t r0 = ((size_t)((b*HDIM + h0 + hi)*WDIM + (w0 + wi))) * COUT;
        size_t r1 = r0 + (size_t)WDIM * COUT;     // pixel i0+8 -> next image row
        #pragma unroll
        for (int nf = 0; nf < 4; ++nf) {
            int col = co0 + warp_n*32 + nf*8 + 2*tig;
            float dx = sdemod[col], dy = sdemod[col + 1];
            float2 v;
            v.x = acc[mf][nf][0] * dx;
            v.y = acc[mf][nf][1] * dy;
            *reinterpret_cast<float2*>(out + r0 + col) = v;
            v.x = acc[mf][nf][2] * dx;
            v.y = acc[mf][nf][3] * dy;
            *reinterpret_cast<float2*>(out + r1 + col) = v;
        }
    }
}

// ---------------- launch ----------------

extern "C" void kernel_launch(void* const* d_in, const int* in_sizes, int n_in,
                              void* d_out, int out_size) {
    (void)in_sizes; (void)n_in; (void)out_size;
    const float* x     = (const float*)d_in[0];   // [16,64,64,256] f32
    const float* style = (const float*)d_in[1];   // [16,256] f32
    const float* kern  = (const float*)d_in[2];   // [3,3,256,256] f32
    float* out = (float*)d_out;                   // [16,64,64,256] f32

    cudaFuncSetAttribute(modconv_kernel,
                         cudaFuncAttributeMaxDynamicSharedMemorySize, SM_TOTAL);

    prep_wT<<<dim3(NTAP, 16), COUT>>>(kern);                 // 144 blocks
    prep_w2<<<CIN, COUT>>>(kern);                            // 256 blocks
    prep_demod_part<<<dim3(BQ, 4), COUT>>>(style);           // 64 blocks
    prep_demod_fin<<<BQ, COUT>>>();                          // 16 blocks
    prep_x<<<(int)(((size_t)BQ*HDIM*WDIM*CIN/4)/256), 256>>>(x, style);
    modconv_kernel<<<(BQ*HDIM*WDIM/(TH*TW)) * (COUT/128), 256, SM_TOTAL>>>(out);
}

// round 12
// speedup vs baseline: 7.0953x; 1.0420x over previous
#include <cuda_runtime.h>
#include <cuda_fp16.h>
#include <cstdint>
#include <cstddef>

#define BQ   16
#define HDIM 64
#define WDIM 64
#define CIN  256
#define COUT 256
#define NTAP 9

#define TH 16
#define TW 8
#define BK 64                      /* ci per stage (f16) */
#define NCHUNK (CIN/BK)            /* 4 */
#define NS (NTAP*NCHUNK)           /* 36 stages */
#define HP (TH+2)
#define WP (TW+2)
#define NPIX (HP*WP)               /* 180 halo pixels */
#define PITCH 144                  /* bytes per pixel row / B row: 128 data + 16 pad */
#define NPART (NTAP*16)            /* 144 demod partial groups */

/* dynamic smem layout (bytes) */
#define SM_DEMOD 0                          /* 256 f32 */
#define SM_XS0   1024
#define XS_BYTES (NPIX*PITCH)               /* 25920 */
#define SM_XS1   (SM_XS0 + XS_BYTES)        /* 26944 */
#define SM_BS    (SM_XS1 + XS_BYTES)        /* 52864 */
#define BS_BYTES (128*PITCH)                /* 18432 */
#define SM_TOTAL (SM_BS + 3*BS_BYTES)       /* 108160 */

// Scratch (device globals; no runtime allocation)
__device__ __half g_xmod[(size_t)BQ*HDIM*WDIM*CIN];   // modulated x, f16 (32 MB)
__device__ __half g_wtT[(size_t)NTAP*COUT*CIN];       // f16 weights [tap][co][ci]
__device__ float  g_dp2[NPART*BQ*COUT];               // demod partials [part][b][co]
__device__ float  g_demod[BQ*COUT];

// ---------------- prep kernels ----------------

// One pass over kern: f16 transpose to [tap][co][ci] AND demod partials per (b,co).
// grid (NTAP, 16 ci-groups), 256 threads = co.
__global__ void prep_w_all(const float* __restrict__ kern,
                           const float* __restrict__ style) {
    __shared__ float s2[16][16];          // [b][i] = (style+1)^2
    int tap = blockIdx.x;
    int cig = blockIdx.y;
    int co  = threadIdx.x;
    {
        int b = threadIdx.x >> 4, i = threadIdx.x & 15;
        float s = style[b*CIN + cig*16 + i] + 1.0f;
        s2[b][i] = s*s;
    }
    __syncthreads();

    float  v2[16];
    __half h[16];
    #pragma unroll
    for (int i = 0; i < 16; ++i) {
        int ci = cig*16 + i;
        float v = kern[((size_t)(tap*CIN + ci))*COUT + co];   // coalesced over co
        h[i]  = __float2half_rn(v);
        v2[i] = v*v;
    }
    // transposed f16 weights: one 32-byte sector per thread
    *reinterpret_cast<uint4*>(g_wtT + ((size_t)(tap*COUT + co))*CIN + cig*16) =
        *reinterpret_cast<const uint4*>(h);
    *reinterpret_cast<uint4*>(g_wtT + ((size_t)(tap*COUT + co))*CIN + cig*16 + 8) =
        *reinterpret_cast<const uint4*>(h + 8);

    // demod partials: fixed-order sums (deterministic)
    const int part = tap*16 + cig;
    #pragma unroll
    for (int b = 0; b < BQ; ++b) {
        float a = 0.0f;
        #pragma unroll
        for (int i = 0; i < 16; ++i) a += s2[b][i] * v2[i];
        g_dp2[(size_t)part*(BQ*COUT) + b*COUT + co] = a;      // coalesced over co
    }
}

// Reduce 144 partials + rsqrt. grid BQ, 256 threads.
__global__ void prep_demod_red() {
    int b = blockIdx.x, co = threadIdx.x;
    float a = 0.0f;
    #pragma unroll 16
    for (int j = 0; j < NPART; ++j)
        a += g_dp2[(size_t)j*(BQ*COUT) + b*COUT + co];
    g_demod[b*COUT + co] = rsqrtf(a + 1e-8f);
}

// Modulate + f16 convert x. grid 4096, 4 float4 per thread (MLP).
__global__ void prep_x(const float* __restrict__ x,
                       const float* __restrict__ style) {
    int i0 = blockIdx.x * 256 + threadIdx.x;
    float4 v[4], s[4];
    #pragma unroll
    for (int j = 0; j < 4; ++j) {
        int i = i0 + j*1048576;               // 4096*256 = 1,048,576 float4 stride
        int e = i << 2;
        int ci = e & (CIN - 1);
        int b  = e >> 20;
        v[j] = reinterpret_cast<const float4*>(x)[i];
        s[j] = reinterpret_cast<const float4*>(style)[(b*CIN + ci) >> 2];
    }
    #pragma unroll
    for (int j = 0; j < 4; ++j) {
        int i = i0 + j*1048576;
        __half2 h01 = __floats2half2_rn(v[j].x*(s[j].x+1.0f), v[j].y*(s[j].y+1.0f));
        __half2 h23 = __floats2half2_rn(v[j].z*(s[j].z+1.0f), v[j].w*(s[j].w+1.0f));
        uint2 pk;
        pk.x = *reinterpret_cast<uint32_t*>(&h01);
        pk.y = *reinterpret_cast<uint32_t*>(&h23);
        reinterpret_cast<uint2*>(g_xmod)[i] = pk;
    }
}

// ---------------- main implicit-GEMM conv (mma.sync f16 m16n8k16) ----------------

__global__ void __launch_bounds__(256, 2) modconv_kernel(float* __restrict__ out) {
    extern __shared__ char smem[];
    float* sdemod = reinterpret_cast<float*>(smem + SM_DEMOD);

    const int tid  = threadIdx.x;
    const int lane = tid & 31;
    const int wid  = tid >> 5;
    const int warp_m = wid >> 2;   // 0..1  (M 2x64)
    const int warp_n = wid & 3;    // 0..3  (N 4x32)
    const int gid = lane >> 2;
    const int tig = lane & 3;

    const int bt     = blockIdx.x;
    const int n_tile = bt & 1;
    const int mt     = bt >> 1;
    const int b      = mt >> 5;
    const int tI     = mt & 31;
    const int h0     = (tI >> 3) << 4;     // *16
    const int w0     = (tI & 7) << 3;      // *8
    const int co0    = n_tile << 7;        // *128

    // A-fragment pixel byte offsets, halo origin (+1,+1)
    int pixo[8];
    #pragma unroll
    for (int mf = 0; mf < 4; ++mf) {
        #pragma unroll
        for (int hf = 0; hf < 2; ++hf) {
            int i  = warp_m*64 + mf*16 + hf*8 + gid;
            int hi = i >> 3, wi = i & 7;
            pixo[mf*2 + hf] = ((hi + 1)*WP + (wi + 1)) * PITCH;
        }
    }

    const uint32_t sbase = (uint32_t)__cvta_generic_to_shared(smem);

    sdemod[tid] = g_demod[b*COUT + tid];

    auto stage_x = [&](int chunk) {
        const uint32_t xb = sbase + ((chunk & 1) ? SM_XS1 : SM_XS0);
        const int ci0 = chunk * BK;
        #pragma unroll 1
        for (int t = tid; t < NPIX * 8; t += 256) {           // 1440 x 16B
            int pix = t >> 3;
            int c4  = t & 7;
            int hh  = pix / WP;
            int ww  = pix - hh * WP;
            int gh  = h0 - 1 + hh;
            int gw  = w0 - 1 + ww;
            bool ok = ((unsigned)gh < HDIM) && ((unsigned)gw < WDIM);
            const void* src = g_xmod;
            if (ok) src = g_xmod + ((size_t)((b*HDIM + gh)*WDIM + gw))*CIN + ci0 + c4*8;
            int sz = ok ? 16 : 0;
            uint32_t dst = xb + (uint32_t)(pix*PITCH + c4*16);
            asm volatile("cp.async.cg.shared.global [%0], [%1], 16, %2;\n"
                         :: "r"(dst), "l"(src), "r"(sz));
        }
    };

    auto stage_b = [&](int f) {
        int tap   = f % NTAP;
        int chunk = f / NTAP;
        uint32_t base = sbase + SM_BS + (f % 3)*BS_BYTES;
        #pragma unroll 1
        for (int t = tid; t < 128 * 8; t += 256) {            // 1024 x 16B
            int n  = t >> 3;
            int c4 = t & 7;
            const void* src = g_wtT + ((size_t)(tap*COUT + co0 + n))*CIN
                              + chunk*BK + c4*8;
            uint32_t dst = base + (uint32_t)(n*PITCH + c4*16);
            asm volatile("cp.async.cg.shared.global [%0], [%1], 16;\n"
                         :: "r"(dst), "l"(src));
        }
    };

    auto fill = [&](int f) {
        if ((f % NTAP) == 0) stage_x(f / NTAP);
        stage_b(f);
        asm volatile("cp.async.commit_group;\n");
    };

    float acc[4][4][4];
    #pragma unroll
    for (int mf = 0; mf < 4; ++mf)
        #pragma unroll
        for (int nf = 0; nf < 4; ++nf)
            #pragma unroll
            for (int r = 0; r < 4; ++r) acc[mf][nf][r] = 0.0f;

    fill(0);
    fill(1);

    #pragma unroll 1
    for (int s = 0; s < NS; ++s) {
        if (s + 2 < NS) asm volatile("cp.async.wait_group 1;\n");
        else            asm volatile("cp.async.wait_group 0;\n");
        // one barrier: stage-s data visible; stage s-1 compute done -> buffers reusable
        __syncthreads();

        if (s + 2 < NS) fill(s + 2);

        const int tap   = s % NTAP;
        const int chunk = s / NTAP;
        const char* xsp = smem + ((chunk & 1) ? SM_XS1 : SM_XS0);
        const char* bsp = smem + SM_BS + (s % 3)*BS_BYTES;
        const int toff = ((tap/3)*WP + (tap%3) - (WP + 1)) * PITCH;

        #pragma unroll
        for (int kk = 0; kk < BK/16; ++kk) {     // 4 k16 iterations
            const int koff = kk*32;
            uint32_t afr[4][4], bfr[4][2];
            #pragma unroll
            for (int mf = 0; mf < 4; ++mf) {
                const char* p0 = xsp + pixo[mf*2 + 0] + toff + koff + tig*4;
                const char* p1 = xsp + pixo[mf*2 + 1] + toff + koff + tig*4;
                afr[mf][0] = *reinterpret_cast<const uint32_t*>(p0);
                afr[mf][1] = *reinterpret_cast<const uint32_t*>(p1);
                afr[mf][2] = *reinterpret_cast<const uint32_t*>(p0 + 16);
                afr[mf][3] = *reinterpret_cast<const uint32_t*>(p1 + 16);
            }
            #pragma unroll
            for (int nf = 0; nf < 4; ++nf) {
                int n = warp_n*32 + nf*8 + gid;
                const char* q = bsp + n*PITCH + koff + tig*4;
                bfr[nf][0] = *reinterpret_cast<const uint32_t*>(q);
                bfr[nf][1] = *reinterpret_cast<const uint32_t*>(q + 16);
            }
            #pragma unroll
            for (int mf = 0; mf < 4; ++mf) {
                #pragma unroll
                for (int nf = 0; nf < 4; ++nf) {
                    asm volatile(
                        "mma.sync.aligned.m16n8k16.row.col.f32.f16.f16.f32 "
                        "{%0,%1,%2,%3}, {%4,%5,%6,%7}, {%8,%9}, {%0,%1,%2,%3};\n"
                        : "+f"(acc[mf][nf][0]), "+f"(acc[mf][nf][1]),
                          "+f"(acc[mf][nf][2]), "+f"(acc[mf][nf][3])
                        : "r"(afr[mf][0]), "r"(afr[mf][1]),
                          "r"(afr[mf][2]), "r"(afr[mf][3]),
                          "r"(bfr[nf][0]), "r"(bfr[nf][1]));
                }
            }
        }
    }

    // Epilogue: scale by demod, coalesced float2 stores
    #pragma unroll
    for (int mf = 0; mf < 4; ++mf) {
        int i0 = warp_m*64 + mf*16 + gid;
        int hi = i0 >> 3, wi = i0 & 7;
        size_t r0 = ((size_t)((b*HDIM + h0 + hi)*WDIM + (w0 + wi))) * COUT;
        size_t r1 = r0 + (size_t)WDIM * COUT;     // pixel i0+8 -> next image row
        #pragma unroll
        for (int nf = 0; nf < 4; ++nf) {
            int col = co0 + warp_n*32 + nf*8 + 2*tig;
            float dx = sdemod[col], dy = sdemod[col + 1];
            float2 v;
            v.x = acc[mf][nf][0] * dx;
            v.y = acc[mf][nf][1] * dy;
            *reinterpret_cast<float2*>(out + r0 + col) = v;
            v.x = acc[mf][nf][2] * dx;
            v.y = acc[mf][nf][3] * dy;
            *reinterpret_cast<float2*>(out + r1 + col) = v;
        }
    }
}

// ---------------- launch ----------------

extern "C" void kernel_launch(void* const* d_in, const int* in_sizes, int n_in,
                              void* d_out, int out_size) {
    (void)in_sizes; (void)n_in; (void)out_size;
    const float* x     = (const float*)d_in[0];   // [16,64,64,256] f32
    const float* style = (const float*)d_in[1];   // [16,256] f32
    const float* kern  = (const float*)d_in[2];   // [3,3,256,256] f32
    float* out = (float*)d_out;                   // [16,64,64,256] f32

    cudaFuncSetAttribute(modconv_kernel,
                         cudaFuncAttributeMaxDynamicSharedMemorySize, SM_TOTAL);

    prep_x<<<4096, 256>>>(x, style);                         // 96 MB, MLP=4
    prep_w_all<<<dim3(NTAP, 16), COUT>>>(kern, style);       // 144 blocks: wT + partials
    prep_demod_red<<<BQ, COUT>>>();                          // 16 blocks: reduce + rsqrt
    modconv_kernel<<<(BQ*HDIM*WDIM/(TH*TW)) * (COUT/128), 256, SM_TOTAL>>>(out);
}

// round 13
// speedup vs baseline: 7.2959x; 1.0283x over previous
#include <cuda_runtime.h>
#include <cuda_fp16.h>
#include <cstdint>
#include <cstddef>

#define BQ   16
#define HDIM 64
#define WDIM 64
#define CIN  256
#define COUT 256
#define NTAP 9

#define TH 16
#define TW 8
#define BK 64                      /* ci per stage (f16) */
#define NCHUNK (CIN/BK)            /* 4 */
#define NS (NTAP*NCHUNK)           /* 36 stages */
#define HP (TH+2)
#define WP (TW+2)
#define NPIX (HP*WP)               /* 180 halo pixels */
#define PITCH 144                  /* bytes per pixel row / B row: 128 data + 16 pad */
#define NPART (NTAP*16)            /* 144 demod partial groups */

/* dynamic smem layout (bytes) */
#define SM_DEMOD 0                          /* 256 f32 */
#define SM_XS0   1024
#define XS_BYTES (NPIX*PITCH)               /* 25920 */
#define SM_XS1   (SM_XS0 + XS_BYTES)        /* 26944 */
#define SM_BS    (SM_XS1 + XS_BYTES)        /* 52864 */
#define BS_BYTES (128*PITCH)                /* 18432 */
#define SM_TOTAL (SM_BS + 3*BS_BYTES)       /* 108160 */

// Scratch (device globals; no runtime allocation)
__device__ __half g_xmod[(size_t)BQ*HDIM*WDIM*CIN];   // modulated x, f16 (32 MB)
__device__ __half g_wtT[(size_t)NTAP*COUT*CIN];       // f16 weights [tap][co][ci]
__device__ float  g_dp2[NPART*BQ*COUT];               // demod partials [part][b][co]
__device__ float  g_demod[BQ*COUT];

// ---------------- prep kernels ----------------

// One pass over kern: f16 transpose to [tap][co][ci] AND demod partials per (b,co).
__global__ void prep_w_all(const float* __restrict__ kern,
                           const float* __restrict__ style) {
    __shared__ float s2[16][16];          // [b][i] = (style+1)^2
    int tap = blockIdx.x;
    int cig = blockIdx.y;
    int co  = threadIdx.x;
    {
        int b = threadIdx.x >> 4, i = threadIdx.x & 15;
        float s = style[b*CIN + cig*16 + i] + 1.0f;
        s2[b][i] = s*s;
    }
    __syncthreads();

    float  v2[16];
    __half h[16];
    #pragma unroll
    for (int i = 0; i < 16; ++i) {
        int ci = cig*16 + i;
        float v = kern[((size_t)(tap*CIN + ci))*COUT + co];   // coalesced over co
        h[i]  = __float2half_rn(v);
        v2[i] = v*v;
    }
    *reinterpret_cast<uint4*>(g_wtT + ((size_t)(tap*COUT + co))*CIN + cig*16) =
        *reinterpret_cast<const uint4*>(h);
    *reinterpret_cast<uint4*>(g_wtT + ((size_t)(tap*COUT + co))*CIN + cig*16 + 8) =
        *reinterpret_cast<const uint4*>(h + 8);

    const int part = tap*16 + cig;
    #pragma unroll
    for (int b = 0; b < BQ; ++b) {
        float a = 0.0f;
        #pragma unroll
        for (int i = 0; i < 16; ++i) a += s2[b][i] * v2[i];
        g_dp2[(size_t)part*(BQ*COUT) + b*COUT + co] = a;
    }
}

__global__ void prep_demod_red() {
    int b = blockIdx.x, co = threadIdx.x;
    float a = 0.0f;
    #pragma unroll 16
    for (int j = 0; j < NPART; ++j)
        a += g_dp2[(size_t)j*(BQ*COUT) + b*COUT + co];
    g_demod[b*COUT + co] = rsqrtf(a + 1e-8f);
}

__global__ void prep_x(const float* __restrict__ x,
                       const float* __restrict__ style) {
    int i0 = blockIdx.x * 256 + threadIdx.x;
    float4 v[4], s[4];
    #pragma unroll
    for (int j = 0; j < 4; ++j) {
        int i = i0 + j*1048576;
        int e = i << 2;
        int ci = e & (CIN - 1);
        int b  = e >> 20;
        v[j] = reinterpret_cast<const float4*>(x)[i];
        s[j] = reinterpret_cast<const float4*>(style)[(b*CIN + ci) >> 2];
    }
    #pragma unroll
    for (int j = 0; j < 4; ++j) {
        int i = i0 + j*1048576;
        __half2 h01 = __floats2half2_rn(v[j].x*(s[j].x+1.0f), v[j].y*(s[j].y+1.0f));
        __half2 h23 = __floats2half2_rn(v[j].z*(s[j].z+1.0f), v[j].w*(s[j].w+1.0f));
        uint2 pk;
        pk.x = *reinterpret_cast<uint32_t*>(&h01);
        pk.y = *reinterpret_cast<uint32_t*>(&h23);
        reinterpret_cast<uint2*>(g_xmod)[i] = pk;
    }
}

// ---------------- main implicit-GEMM conv (mma.sync f16 + ldmatrix) ----------------

__global__ void __launch_bounds__(256, 2) modconv_kernel(float* __restrict__ out) {
    extern __shared__ char smem[];
    float* sdemod = reinterpret_cast<float*>(smem + SM_DEMOD);

    const int tid  = threadIdx.x;
    const int lane = tid & 31;
    const int wid  = tid >> 5;
    const int warp_m = wid >> 2;   // 0..1  (M 2x64)
    const int warp_n = wid & 3;    // 0..3  (N 4x32)
    const int gid = lane >> 2;
    const int tig = lane & 3;

    const int bt     = blockIdx.x;
    const int n_tile = bt & 1;
    const int mt     = bt >> 1;
    const int b      = mt >> 5;
    const int tI     = mt & 31;
    const int h0     = (tI >> 3) << 4;     // *16
    const int w0     = (tI & 7) << 3;      // *8
    const int co0    = n_tile << 7;        // *128

    const uint32_t sbase = (uint32_t)__cvta_generic_to_shared(smem);

    // ldmatrix A addresses: per mf, this lane supplies pixel row (lane&15),
    // k-half (lane>>4). Offsets relative to xs base.
    uint32_t a_off[4];
    #pragma unroll
    for (int mf = 0; mf < 4; ++mf) {
        int i  = warp_m*64 + mf*16 + (lane & 15);
        int hi = i >> 3, wi = i & 7;
        a_off[mf] = (uint32_t)(((hi + 1)*WP + (wi + 1)) * PITCH + (lane >> 4)*16);
    }
    // ldmatrix B addresses: per nf, lane supplies n row (lane&7), k-half ((lane>>3)&1).
    uint32_t b_off[4];
    #pragma unroll
    for (int nf = 0; nf < 4; ++nf) {
        int n = warp_n*32 + nf*8 + (lane & 7);
        b_off[nf] = (uint32_t)(n*PITCH + ((lane >> 3) & 1)*16);
    }

    sdemod[tid] = g_demod[b*COUT + tid];

    auto stage_x = [&](int chunk) {
        const uint32_t xb = sbase + ((chunk & 1) ? SM_XS1 : SM_XS0);
        const int ci0 = chunk * BK;
        #pragma unroll 1
        for (int t = tid; t < NPIX * 8; t += 256) {           // 1440 x 16B
            int pix = t >> 3;
            int c4  = t & 7;
            int hh  = pix / WP;
            int ww  = pix - hh * WP;
            int gh  = h0 - 1 + hh;
            int gw  = w0 - 1 + ww;
            bool ok = ((unsigned)gh < HDIM) && ((unsigned)gw < WDIM);
            const void* src = g_xmod;
            if (ok) src = g_xmod + ((size_t)((b*HDIM + gh)*WDIM + gw))*CIN + ci0 + c4*8;
            int sz = ok ? 16 : 0;
            uint32_t dst = xb + (uint32_t)(pix*PITCH + c4*16);
            asm volatile("cp.async.cg.shared.global [%0], [%1], 16, %2;\n"
                         :: "r"(dst), "l"(src), "r"(sz));
        }
    };

    auto stage_b = [&](int f) {
        int tap   = f % NTAP;
        int chunk = f / NTAP;
        uint32_t base = sbase + SM_BS + (f % 3)*BS_BYTES;
        #pragma unroll 1
        for (int t = tid; t < 128 * 8; t += 256) {            // 1024 x 16B
            int n  = t >> 3;
            int c4 = t & 7;
            const void* src = g_wtT + ((size_t)(tap*COUT + co0 + n))*CIN
                              + chunk*BK + c4*8;
            uint32_t dst = base + (uint32_t)(n*PITCH + c4*16);
            asm volatile("cp.async.cg.shared.global [%0], [%1], 16;\n"
                         :: "r"(dst), "l"(src));
        }
    };

    auto fill = [&](int f) {
        if ((f % NTAP) == 0) stage_x(f / NTAP);
        stage_b(f);
        asm volatile("cp.async.commit_group;\n");
    };

    float acc[4][4][4];
    #pragma unroll
    for (int mf = 0; mf < 4; ++mf)
        #pragma unroll
        for (int nf = 0; nf < 4; ++nf)
            #pragma unroll
            for (int r = 0; r < 4; ++r) acc[mf][nf][r] = 0.0f;

    fill(0);
    fill(1);

    #pragma unroll 1
    for (int s = 0; s < NS; ++s) {
        if (s + 2 < NS) asm volatile("cp.async.wait_group 1;\n");
        else            asm volatile("cp.async.wait_group 0;\n");
        // one barrier: stage-s data visible; stage s-1 compute done -> buffers reusable
        __syncthreads();

        if (s + 2 < NS) fill(s + 2);

        const int tap   = s % NTAP;
        const int chunk = s / NTAP;
        const uint32_t xsp = sbase + ((chunk & 1) ? SM_XS1 : SM_XS0);
        const uint32_t bsp = sbase + SM_BS + (s % 3)*BS_BYTES;
        const int toff = ((tap/3)*WP + (tap%3) - (WP + 1)) * PITCH;

        #pragma unroll
        for (int kk = 0; kk < BK/16; ++kk) {     // 4 k16 iterations
            const int koff = kk*32;
            uint32_t afr[4][4], bfr[4][2];
            #pragma unroll
            for (int mf = 0; mf < 4; ++mf) {
                uint32_t addr = xsp + a_off[mf] + (uint32_t)(toff + koff);
                asm volatile(
                    "ldmatrix.sync.aligned.m8n8.x4.shared.b16 {%0,%1,%2,%3}, [%4];"
                    : "=r"(afr[mf][0]), "=r"(afr[mf][1]),
                      "=r"(afr[mf][2]), "=r"(afr[mf][3])
                    : "r"(addr));
            }
            #pragma unroll
            for (int nf = 0; nf < 4; ++nf) {
                uint32_t addr = bsp + b_off[nf] + (uint32_t)koff;
                asm volatile(
                    "ldmatrix.sync.aligned.m8n8.x2.shared.b16 {%0,%1}, [%2];"
                    : "=r"(bfr[nf][0]), "=r"(bfr[nf][1])
                    : "r"(addr));
            }
            #pragma unroll
            for (int mf = 0; mf < 4; ++mf) {
                #pragma unroll
                for (int nf = 0; nf < 4; ++nf) {
                    asm volatile(
                        "mma.sync.aligned.m16n8k16.row.col.f32.f16.f16.f32 "
                        "{%0,%1,%2,%3}, {%4,%5,%6,%7}, {%8,%9}, {%0,%1,%2,%3};\n"
                        : "+f"(acc[mf][nf][0]), "+f"(acc[mf][nf][1]),
                          "+f"(acc[mf][nf][2]), "+f"(acc[mf][nf][3])
                        : "r"(afr[mf][0]), "r"(afr[mf][1]),
                          "r"(afr[mf][2]), "r"(afr[mf][3]),
                          "r"(bfr[nf][0]), "r"(bfr[nf][1]));
                }
            }
        }
    }

    // Epilogue: scale by demod, coalesced float2 stores
    #pragma unroll
    for (int mf = 0; mf < 4; ++mf) {
        int i0 = warp_m*64 + mf*16 + gid;
        int hi = i0 >> 3, wi = i0 & 7;
        size_t r0 = ((size_t)((b*HDIM + h0 + hi)*WDIM + (w0 + wi))) * COUT;
        size_t r1 = r0 + (size_t)WDIM * COUT;     // pixel i0+8 -> next image row
        #pragma unroll
        for (int nf = 0; nf < 4; ++nf) {
            int col = co0 + warp_n*32 + nf*8 + 2*tig;
            float dx = sdemod[col], dy = sdemod[col + 1];
            float2 v;
            v.x = acc[mf][nf][0] * dx;
            v.y = acc[mf][nf][1] * dy;
            *reinterpret_cast<float2*>(out + r0 + col) = v;
            v.x = acc[mf][nf][2] * dx;
            v.y = acc[mf][nf][3] * dy;
            *reinterpret_cast<float2*>(out + r1 + col) = v;
        }
    }
}

// ---------------- launch ----------------

extern "C" void kernel_launch(void* const* d_in, const int* in_sizes, int n_in,
                              void* d_out, int out_size) {
    (void)in_sizes; (void)n_in; (void)out_size;
    const float* x     = (const float*)d_in[0];   // [16,64,64,256] f32
    const float* style = (const float*)d_in[1];   // [16,256] f32
    const float* kern  = (const float*)d_in[2];   // [3,3,256,256] f32
    float* out = (float*)d_out;                   // [16,64,64,256] f32

    cudaFuncSetAttribute(modconv_kernel,
                         cudaFuncAttributeMaxDynamicSharedMemorySize, SM_TOTAL);

    prep_x<<<4096, 256>>>(x, style);                         // 96 MB, MLP=4
    prep_w_all<<<dim3(NTAP, 16), COUT>>>(kern, style);       // 144 blocks
    prep_demod_red<<<BQ, COUT>>>();                          // 16 blocks
    modconv_kernel<<<(BQ*HDIM*WDIM/(TH*TW)) * (COUT/128), 256, SM_TOTAL>>>(out);
}